// round 7
// baseline (speedup 1.0000x reference)
#include <cuda_runtime.h>
#include <cuda_fp16.h>
#include <cstdint>

#define NN 8192
#define FD 128

// ---------------- global scratch (allocation-free rule) ----------------
__device__ __half g_Bhi[NN * FD];     // Wh fp16
__device__ float4 g_E1[NN];           // {f1, e^f1, e^{0.2 f1}, 0}
__device__ float4 g_E2[NN];           // {f2, e^f2, e^{0.2 f2}, 0}

// ---------------- helpers ----------------
__device__ __forceinline__ uint32_t smem_u32(const void* p) {
    uint32_t a;
    asm("{ .reg .u64 t; cvta.to.shared.u64 t, %1; cvt.u32.u64 %0, t; }" : "=r"(a) : "l"(p));
    return a;
}
__device__ __forceinline__ float slctf(float a, float b, float c) {
    float d; asm("slct.f32.f32 %0, %1, %2, %3;" : "=f"(d) : "f"(a), "f"(b), "f"(c));
    return d;  // c >= 0 ? a : b
}
__device__ __forceinline__ uint32_t f16x2(float hi, float lo) {
    uint32_t r; asm("cvt.rn.f16x2.f32 %0, %1, %2;" : "=r"(r) : "f"(hi), "f"(lo));
    return r;
}
__device__ __forceinline__ void cp16(uint32_t dst, const void* src) {
    asm volatile("cp.async.cg.shared.global [%0], [%1], 16;" :: "r"(dst), "l"(src));
}
__device__ __forceinline__ void cp_commit() {
    asm volatile("cp.async.commit_group;" ::: "memory");
}
__device__ __forceinline__ void cp_wait1() {
    asm volatile("cp.async.wait_group 1;" ::: "memory");
}
__device__ __forceinline__ void cp_wait0() {
    asm volatile("cp.async.wait_group 0;" ::: "memory");
}
__device__ __forceinline__ void ldsm_x4(uint32_t* r, uint32_t addr) {
    asm volatile("ldmatrix.sync.aligned.m8n8.x4.shared.b16 {%0,%1,%2,%3}, [%4];"
                 : "=r"(r[0]), "=r"(r[1]), "=r"(r[2]), "=r"(r[3]) : "r"(addr));
}
__device__ __forceinline__ void ldsm_x4t(uint32_t* r, uint32_t addr) {
    asm volatile("ldmatrix.sync.aligned.m8n8.x4.trans.shared.b16 {%0,%1,%2,%3}, [%4];"
                 : "=r"(r[0]), "=r"(r[1]), "=r"(r[2]), "=r"(r[3]) : "r"(addr));
}
__device__ __forceinline__ void mma16816(float* d, const uint32_t* a, const uint32_t* b) {
    asm volatile(
        "mma.sync.aligned.m16n8k16.row.col.f32.f16.f16.f32 "
        "{%0,%1,%2,%3},{%4,%5,%6,%7},{%8,%9},{%0,%1,%2,%3};"
        : "+f"(d[0]), "+f"(d[1]), "+f"(d[2]), "+f"(d[3])
        : "r"(a[0]), "r"(a[1]), "r"(a[2]), "r"(a[3]), "r"(b[0]), "r"(b[1]));
}

// ---------------- Kernel A: Wh = h @ W + fp16 convert + fused f/exp vectors ----------------
__global__ void __launch_bounds__(256) wh_kernel(const float* __restrict__ h,
                                                 const float* __restrict__ W,
                                                 const float* __restrict__ a) {
    extern __shared__ float sm[];
    float* sW = sm;              // 128x128
    float* sh = sm + 16384;      // 32x128
    float* sa = sh + 4096;       // 256
    int tid = threadIdx.x;
    int i0 = blockIdx.x * 32;

    {
        float4* wd = (float4*)sW; const float4* ws = (const float4*)W;
        #pragma unroll
        for (int p = 0; p < 16; p++) wd[tid + p * 256] = ws[tid + p * 256];
        float4* hd = (float4*)sh; const float4* hs = (const float4*)(h + (size_t)i0 * FD);
        #pragma unroll
        for (int p = 0; p < 4; p++) hd[tid + p * 256] = hs[tid + p * 256];
        sa[tid] = a[tid];
    }
    __syncthreads();

    int row = tid >> 3;
    int seg = (tid & 7) * 16;
    float acc[16];
    #pragma unroll
    for (int q = 0; q < 16; q++) acc[q] = 0.f;

    #pragma unroll 4
    for (int k = 0; k < FD; k++) {
        float hv = sh[row * FD + k];
        const float* wr = sW + k * FD + seg;
        #pragma unroll
        for (int q = 0; q < 16; q++) acc[q] = fmaf(hv, wr[q], acc[q]);
    }

    uint32_t hp[8];
    #pragma unroll
    for (int q = 0; q < 8; q++) hp[q] = f16x2(acc[2 * q + 1], acc[2 * q]);
    {
        uint32_t* dh = (uint32_t*)(g_Bhi + (size_t)(i0 + row) * FD + seg);
        *(uint4*)dh = make_uint4(hp[0], hp[1], hp[2], hp[3]);
        *(uint4*)(dh + 4) = make_uint4(hp[4], hp[5], hp[6], hp[7]);
    }

    float p1 = 0.f, p2 = 0.f;
    #pragma unroll
    for (int q = 0; q < 16; q++) {
        p1 = fmaf(acc[q], sa[seg + q], p1);
        p2 = fmaf(acc[q], sa[128 + seg + q], p2);
    }
    #pragma unroll
    for (int o = 1; o < 8; o <<= 1) {
        p1 += __shfl_xor_sync(0xffffffffu, p1, o);
        p2 += __shfl_xor_sync(0xffffffffu, p2, o);
    }
    if ((tid & 7) == 0) {
        g_E1[i0 + row] = make_float4(p1, expf(p1), expf(0.2f * p1), 0.f);
        g_E2[i0 + row] = make_float4(p2, expf(p2), expf(0.2f * p2), 0.f);
    }
}

// ---------------- Kernel B: main fused GAT ----------------
// 128 CTAs x 64 rows, full j range. 256 threads = 8 warps (2 warp-rows x 4 warp-cols).
// A: 64 x 64 fp16 weights, row stride 144B (dbl-buffered).
// B: 64k x 128n fp16, row stride 272B (dbl-buffered, cp.async).
#define ABUF 9216
#define BBUF 17408
#define OFF_A 0
#define OFF_B (2 * ABUF)               // 18432
#define OFF_E1 (OFF_B + 2 * BBUF)      // 53248
#define SMEM_MAIN (OFF_E1 + 64 * 16)   // 54272

struct Pref {
    int4 av[4];
    float4 e2[4];
};

__device__ __forceinline__ void prefetch(Pref& P, int i0, int j0,
                                         const int* __restrict__ adj, int lane, int wid) {
    int jj = (lane & 15) * 4;
    int rowpar = lane >> 4;
    #pragma unroll
    for (int q = 0; q < 4; q++) P.e2[q] = g_E2[j0 + jj + q];
    #pragma unroll
    for (int p = 0; p < 4; p++) {
        int row = p * 16 + wid * 2 + rowpar;
        P.av[p] = *(const int4*)(adj + (size_t)(i0 + row) * NN + j0 + jj);
    }
}

// one row of weights (16 j per thread-group) for chunk in buffer `buf`
__device__ __forceinline__ void gen_piece(char* smem, int buf, const Pref& P,
                                          int p, int lane, int wid) {
    const float4* sE1 = (const float4*)(smem + OFF_E1);
    int row = p * 16 + wid * 2 + (lane >> 4);
    float4 e1 = sE1[row];
    float w[4];
    #pragma unroll
    for (int q = 0; q < 4; q++) {
        float f2x = (q == 0) ? P.e2[0].x : (q == 1) ? P.e2[1].x : (q == 2) ? P.e2[2].x : P.e2[3].x;
        float Ep  = (q == 0) ? P.e2[0].y : (q == 1) ? P.e2[1].y : (q == 2) ? P.e2[2].y : P.e2[3].y;
        float En  = (q == 0) ? P.e2[0].z : (q == 1) ? P.e2[1].z : (q == 2) ? P.e2[2].z : P.e2[3].z;
        float z = e1.x + f2x;
        w[q] = slctf(e1.y, e1.z, z) * slctf(Ep, En, z);
    }
    if (P.av[p].x <= 0) w[0] = 0.f;
    if (P.av[p].y <= 0) w[1] = 0.f;
    if (P.av[p].z <= 0) w[2] = 0.f;
    if (P.av[p].w <= 0) w[3] = 0.f;
    *(uint2*)(smem + OFF_A + buf * ABUF + row * 144 + (lane & 15) * 8) =
        make_uint2(f16x2(w[1], w[0]), f16x2(w[3], w[2]));
}

__device__ __forceinline__ void stage_B(int buf, int j0, int tid, uint32_t sb) {
    #pragma unroll
    for (int p = 0; p < 4; p++) {
        int idx = tid + p * 256;
        int row = idx >> 4, seg = idx & 15;
        cp16(sb + OFF_B + buf * BBUF + row * 272 + seg * 16,
             g_Bhi + (size_t)(j0 + row) * FD + seg * 8);
    }
}

__global__ void __launch_bounds__(256, 1) gat_main_kernel(const int* __restrict__ adj,
                                                          float* __restrict__ out) {
    extern __shared__ char smem[];
    uint32_t sb = smem_u32(smem);
    int tid = threadIdx.x, lane = tid & 31, wid = tid >> 5;
    int i0 = blockIdx.x * 64;
    int wr = wid & 1, wc = wid >> 1;

    if (tid < 64) ((float4*)(smem + OFF_E1))[tid] = g_E1[i0 + tid];

    float acc[2][4][4];
    float dacc[2][4];
    #pragma unroll
    for (int s = 0; s < 2; s++) {
        #pragma unroll
        for (int t = 0; t < 4; t++)
            #pragma unroll
            for (int q = 0; q < 4; q++) acc[s][t][q] = 0.f;
        #pragma unroll
        for (int q = 0; q < 4; q++) dacc[s][q] = 0.f;
    }
    uint32_t bones[2];
    bones[0] = bones[1] = (lane < 4) ? 0x3C003C00u : 0u;  // ones-column fragment

    Pref P;
    prefetch(P, i0, 0, adj, lane, wid);
    stage_B(0, 0, tid, sb);
    cp_commit();
    __syncthreads();                       // E1 visible
    #pragma unroll
    for (int p = 0; p < 4; p++) gen_piece(smem, 0, P, p, lane, wid);

    for (int c = 0; c < 128; c++) {
        __syncthreads();                   // A(c)+prior-buffer reuse guard
        if (c + 1 < 128) {
            prefetch(P, i0, (c + 1) * 64, adj, lane, wid);
            stage_B((c + 1) & 1, (c + 1) * 64, tid, sb);
            cp_commit();
            cp_wait1();                    // B(c) ready
        } else {
            cp_wait0();
        }

        int buf = c & 1;
        uint32_t Ab = sb + OFF_A + buf * ABUF;
        uint32_t Bb = sb + OFF_B + buf * BBUF;
        #pragma unroll
        for (int ks = 0; ks < 4; ks++) {
            uint32_t afr[2][4];
            ldsm_x4(afr[0], Ab + (wr * 32 + (lane & 15)) * 144 + ks * 32 + (lane >> 4) * 16);
            ldsm_x4(afr[1], Ab + (wr * 32 + 16 + (lane & 15)) * 144 + ks * 32 + (lane >> 4) * 16);
            #pragma unroll
            for (int t2 = 0; t2 < 2; t2++) {
                uint32_t bf[4];
                ldsm_x4t(bf, Bb + (ks * 16 + (lane & 7) + ((lane >> 3) & 1) * 8) * 272
                               + (wc * 4 + t2 * 2 + (lane >> 4)) * 16);
                mma16816(acc[0][2 * t2],     afr[0], bf);
                mma16816(acc[0][2 * t2 + 1], afr[0], bf + 2);
                mma16816(acc[1][2 * t2],     afr[1], bf);
                mma16816(acc[1][2 * t2 + 1], afr[1], bf + 2);
            }
            if (wc == 0) {
                mma16816(dacc[0], afr[0], bones);
                mma16816(dacc[1], afr[1], bones);
            }
            if (c + 1 < 128) gen_piece(smem, (c + 1) & 1, P, ks, lane, wid);  // overlap fma with tensor
        }
    }

    // ---- epilogue: denominators to smem, normalize, store ----
    __syncthreads();
    float* ssum = (float*)smem;   // A buffers dead now
    if (wc == 0 && (lane & 3) == 0) {
        #pragma unroll
        for (int s = 0; s < 2; s++) {
            int r = wr * 32 + s * 16 + (lane >> 2);
            ssum[r] = dacc[s][0];
            ssum[r + 8] = dacc[s][2];
        }
    }
    __syncthreads();
    #pragma unroll
    for (int s = 0; s < 2; s++) {
        int rA = wr * 32 + s * 16 + (lane >> 2);
        float inv0 = 1.0f / ssum[rA];
        float inv1 = 1.0f / ssum[rA + 8];
        #pragma unroll
        for (int t = 0; t < 4; t++) {
            int col = wc * 32 + t * 8 + (lane & 3) * 2;
            *(float2*)&out[(size_t)(i0 + rA) * FD + col] =
                make_float2(acc[s][t][0] * inv0, acc[s][t][1] * inv0);
            *(float2*)&out[(size_t)(i0 + rA + 8) * FD + col] =
                make_float2(acc[s][t][2] * inv1, acc[s][t][3] * inv1);
        }
    }
}

// ---------------- launch ----------------
extern "C" void kernel_launch(void* const* d_in, const int* in_sizes, int n_in,
                              void* d_out, int out_size) {
    const float* h   = (const float*)d_in[0];
    const int*   adj = (const int*)d_in[1];
    const float* W   = (const float*)d_in[2];
    const float* a   = (const float*)d_in[3];
    float* out = (float*)d_out;
    (void)in_sizes; (void)n_in; (void)out_size;

    cudaFuncSetAttribute(wh_kernel, cudaFuncAttributeMaxDynamicSharedMemorySize, 82944);
    cudaFuncSetAttribute(gat_main_kernel, cudaFuncAttributeMaxDynamicSharedMemorySize, SMEM_MAIN);

    wh_kernel<<<NN / 32, 256, 82944>>>(h, W, a);
    gat_main_kernel<<<128, 256, SMEM_MAIN>>>(adj, out);
}

// round 10
// speedup vs baseline: 1.2318x; 1.2318x over previous
#include <cuda_runtime.h>
#include <cuda_fp16.h>
#include <cstdint>

#define NN 8192
#define FD 128

// ---------------- global scratch (allocation-free rule) ----------------
__device__ __half g_Bhi[NN * FD];     // Wh fp16
__device__ float4 g_E1[NN];           // {f1, e^f1, e^{0.2 f1}, 0}
__device__ float4 g_E2[NN];           // {f2, e^f2, e^{0.2 f2}, 0}

// ---------------- helpers ----------------
__device__ __forceinline__ uint32_t smem_u32(const void* p) {
    uint32_t a;
    asm("{ .reg .u64 t; cvta.to.shared.u64 t, %1; cvt.u32.u64 %0, t; }" : "=r"(a) : "l"(p));
    return a;
}
__device__ __forceinline__ float slctf(float a, float b, float c) {
    float d; asm("slct.f32.f32 %0, %1, %2, %3;" : "=f"(d) : "f"(a), "f"(b), "f"(c));
    return d;  // c >= 0 ? a : b
}
__device__ __forceinline__ uint32_t f16x2(float hi, float lo) {
    uint32_t r; asm("cvt.rn.f16x2.f32 %0, %1, %2;" : "=r"(r) : "f"(hi), "f"(lo));
    return r;
}
__device__ __forceinline__ void cp16(uint32_t dst, const void* src) {
    asm volatile("cp.async.cg.shared.global [%0], [%1], 16;" :: "r"(dst), "l"(src));
}
__device__ __forceinline__ void cp_commit() {
    asm volatile("cp.async.commit_group;" ::: "memory");
}
__device__ __forceinline__ void cp_wait1() {
    asm volatile("cp.async.wait_group 1;" ::: "memory");
}
__device__ __forceinline__ void cp_wait0() {
    asm volatile("cp.async.wait_group 0;" ::: "memory");
}
__device__ __forceinline__ void ldsm_x4(uint32_t* r, uint32_t addr) {
    asm volatile("ldmatrix.sync.aligned.m8n8.x4.shared.b16 {%0,%1,%2,%3}, [%4];"
                 : "=r"(r[0]), "=r"(r[1]), "=r"(r[2]), "=r"(r[3]) : "r"(addr));
}
__device__ __forceinline__ void ldsm_x4t(uint32_t* r, uint32_t addr) {
    asm volatile("ldmatrix.sync.aligned.m8n8.x4.trans.shared.b16 {%0,%1,%2,%3}, [%4];"
                 : "=r"(r[0]), "=r"(r[1]), "=r"(r[2]), "=r"(r[3]) : "r"(addr));
}
__device__ __forceinline__ void mma16816(float* d, const uint32_t* a, const uint32_t* b) {
    asm volatile(
        "mma.sync.aligned.m16n8k16.row.col.f32.f16.f16.f32 "
        "{%0,%1,%2,%3},{%4,%5,%6,%7},{%8,%9},{%0,%1,%2,%3};"
        : "+f"(d[0]), "+f"(d[1]), "+f"(d[2]), "+f"(d[3])
        : "r"(a[0]), "r"(a[1]), "r"(a[2]), "r"(a[3]), "r"(b[0]), "r"(b[1]));
}

// ---------------- Kernel A: Wh = h @ W + fp16 convert + fused f/exp vectors ----------------
// 128 CTAs x 64 rows, 512 threads. Thread = 4 rows x 4 consecutive cols.
// W LDS.128 (lane stride 16B -> conflict-free), h broadcast LDS.
__global__ void __launch_bounds__(512) wh_kernel(const float* __restrict__ h,
                                                 const float* __restrict__ W,
                                                 const float* __restrict__ a) {
    extern __shared__ float sm[];
    float* sW = sm;              // 128x128
    float* sh = sm + 16384;      // 64x128
    float* sa = sh + 8192;       // 256
    int tid = threadIdx.x;
    int i0 = blockIdx.x * 64;

    {
        float4* wd = (float4*)sW; const float4* ws = (const float4*)W;
        #pragma unroll
        for (int p = 0; p < 8; p++) wd[tid + p * 512] = ws[tid + p * 512];
        float4* hd = (float4*)sh; const float4* hs = (const float4*)(h + (size_t)i0 * FD);
        #pragma unroll
        for (int p = 0; p < 4; p++) hd[tid + p * 512] = hs[tid + p * 512];
        if (tid < 256) sa[tid] = a[tid];
    }
    __syncthreads();

    int rg = tid >> 5;          // warp = row group (4 rows)
    int ct = tid & 31;          // col thread
    int r0 = rg * 4, c0 = ct * 4;
    float acc[4][4];
    #pragma unroll
    for (int r = 0; r < 4; r++)
        #pragma unroll
        for (int q = 0; q < 4; q++) acc[r][q] = 0.f;

    #pragma unroll 4
    for (int k = 0; k < FD; k++) {
        float4 wv = *(const float4*)(sW + k * FD + c0);
        #pragma unroll
        for (int r = 0; r < 4; r++) {
            float hv = sh[(r0 + r) * FD + k];
            acc[r][0] = fmaf(hv, wv.x, acc[r][0]);
            acc[r][1] = fmaf(hv, wv.y, acc[r][1]);
            acc[r][2] = fmaf(hv, wv.z, acc[r][2]);
            acc[r][3] = fmaf(hv, wv.w, acc[r][3]);
        }
    }

    // fp16 store (coalesced: 32 lanes x 8B = 256B)
    #pragma unroll
    for (int r = 0; r < 4; r++) {
        *(uint2*)(g_Bhi + (size_t)(i0 + r0 + r) * FD + c0) =
            make_uint2(f16x2(acc[r][1], acc[r][0]), f16x2(acc[r][3], acc[r][2]));
    }

    // f1/f2 + exp (warp-level reduce; warp owns 4 rows)
    #pragma unroll
    for (int r = 0; r < 4; r++) {
        float p1 = acc[r][0] * sa[c0] + acc[r][1] * sa[c0 + 1]
                 + acc[r][2] * sa[c0 + 2] + acc[r][3] * sa[c0 + 3];
        float p2 = acc[r][0] * sa[128 + c0] + acc[r][1] * sa[128 + c0 + 1]
                 + acc[r][2] * sa[128 + c0 + 2] + acc[r][3] * sa[128 + c0 + 3];
        #pragma unroll
        for (int o = 1; o < 32; o <<= 1) {
            p1 += __shfl_xor_sync(0xffffffffu, p1, o);
            p2 += __shfl_xor_sync(0xffffffffu, p2, o);
        }
        if (ct == 0) {
            g_E1[i0 + r0 + r] = make_float4(p1, expf(p1), expf(0.2f * p1), 0.f);
            g_E2[i0 + r0 + r] = make_float4(p2, expf(p2), expf(0.2f * p2), 0.f);
        }
    }
}

// ---------------- Kernel B: main fused GAT ----------------
// 128 CTAs x 64 rows, full j. 512 threads = 16 warps (2 warp-rows x 8 warp-cols).
// A: 64 x 64 fp16 weights, stride 144B (dbl-buffered).
// B: 64k x 128n fp16, stride 272B (dbl-buffered, cp.async).
#define ABUF 9216
#define BBUF 17408
#define OFF_A 0
#define OFF_B (2 * ABUF)               // 18432
#define OFF_E1 (OFF_B + 2 * BBUF)      // 53248
#define SMEM_MAIN (OFF_E1 + 64 * 16)   // 54272

struct Pref {
    int4 av[2];
    float4 e2[4];
};

__device__ __forceinline__ void prefetch(Pref& P, int i0, int j0,
                                         const int* __restrict__ adj, int lane, int wid) {
    int jj = (lane & 15) * 4;
    int rowpar = lane >> 4;
    #pragma unroll
    for (int q = 0; q < 4; q++) P.e2[q] = g_E2[j0 + jj + q];
    #pragma unroll
    for (int p = 0; p < 2; p++) {
        int row = p * 32 + wid * 2 + rowpar;
        P.av[p] = *(const int4*)(adj + (size_t)(i0 + row) * NN + j0 + jj);
    }
}

__device__ __forceinline__ void gen_piece(char* smem, int buf, const Pref& P,
                                          int p, int lane, int wid) {
    const float4* sE1 = (const float4*)(smem + OFF_E1);
    int row = p * 32 + wid * 2 + (lane >> 4);
    float4 e1 = sE1[row];
    float w[4];
    #pragma unroll
    for (int q = 0; q < 4; q++) {
        float f2x = (q == 0) ? P.e2[0].x : (q == 1) ? P.e2[1].x : (q == 2) ? P.e2[2].x : P.e2[3].x;
        float Ep  = (q == 0) ? P.e2[0].y : (q == 1) ? P.e2[1].y : (q == 2) ? P.e2[2].y : P.e2[3].y;
        float En  = (q == 0) ? P.e2[0].z : (q == 1) ? P.e2[1].z : (q == 2) ? P.e2[2].z : P.e2[3].z;
        float z = e1.x + f2x;
        w[q] = slctf(e1.y, e1.z, z) * slctf(Ep, En, z);
    }
    if (P.av[p].x <= 0) w[0] = 0.f;
    if (P.av[p].y <= 0) w[1] = 0.f;
    if (P.av[p].z <= 0) w[2] = 0.f;
    if (P.av[p].w <= 0) w[3] = 0.f;
    *(uint2*)(smem + OFF_A + buf * ABUF + row * 144 + (lane & 15) * 8) =
        make_uint2(f16x2(w[1], w[0]), f16x2(w[3], w[2]));
}

__device__ __forceinline__ void stage_B(int buf, int j0, int tid, uint32_t sb) {
    #pragma unroll
    for (int p = 0; p < 2; p++) {
        int idx = tid + p * 512;
        int row = idx >> 4, seg = idx & 15;
        cp16(sb + OFF_B + buf * BBUF + row * 272 + seg * 16,
             g_Bhi + (size_t)(j0 + row) * FD + seg * 8);
    }
}

__global__ void __launch_bounds__(512, 1) gat_main_kernel(const int* __restrict__ adj,
                                                          float* __restrict__ out) {
    extern __shared__ char smem[];
    uint32_t sb = smem_u32(smem);
    int tid = threadIdx.x, lane = tid & 31, wid = tid >> 5;
    int i0 = blockIdx.x * 64;
    int wr = wid & 1, wc = wid >> 1;   // 2 warp-rows x 8 warp-cols

    if (tid < 64) ((float4*)(smem + OFF_E1))[tid] = g_E1[i0 + tid];

    float acc[2][2][4];
    float dacc[2][4];
    #pragma unroll
    for (int s = 0; s < 2; s++) {
        #pragma unroll
        for (int t = 0; t < 2; t++)
            #pragma unroll
            for (int q = 0; q < 4; q++) acc[s][t][q] = 0.f;
        #pragma unroll
        for (int q = 0; q < 4; q++) dacc[s][q] = 0.f;
    }
    uint32_t bones[2];
    bones[0] = bones[1] = (lane < 4) ? 0x3C003C00u : 0u;  // ones-column fragment

    Pref P;
    prefetch(P, i0, 0, adj, lane, wid);
    stage_B(0, 0, tid, sb);
    cp_commit();
    __syncthreads();                       // E1 visible
    #pragma unroll
    for (int p = 0; p < 2; p++) gen_piece(smem, 0, P, p, lane, wid);

    for (int c = 0; c < 128; c++) {
        __syncthreads();                   // A(c) ready + prior-buffer reuse guard
        if (c + 1 < 128) {
            prefetch(P, i0, (c + 1) * 64, adj, lane, wid);
            stage_B((c + 1) & 1, (c + 1) * 64, tid, sb);
            cp_commit();
            cp_wait1();                    // B(c) ready
        } else {
            cp_wait0();
        }

        int buf = c & 1;
        uint32_t Ab = sb + OFF_A + buf * ABUF;
        uint32_t Bb = sb + OFF_B + buf * BBUF;
        #pragma unroll
        for (int ks = 0; ks < 4; ks++) {
            uint32_t afr[2][4];
            ldsm_x4(afr[0], Ab + (wr * 32 + (lane & 15)) * 144 + ks * 32 + (lane >> 4) * 16);
            ldsm_x4(afr[1], Ab + (wr * 32 + 16 + (lane & 15)) * 144 + ks * 32 + (lane >> 4) * 16);
            uint32_t bf[4];
            ldsm_x4t(bf, Bb + (ks * 16 + (lane & 7) + ((lane >> 3) & 1) * 8) * 272
                           + (wc * 2 + (lane >> 4)) * 16);
            mma16816(acc[0][0], afr[0], bf);
            mma16816(acc[0][1], afr[0], bf + 2);
            mma16816(acc[1][0], afr[1], bf);
            mma16816(acc[1][1], afr[1], bf + 2);
            if (wc == 0) {
                mma16816(dacc[0], afr[0], bones);
                mma16816(dacc[1], afr[1], bones);
            }
            if (ks < 2 && c + 1 < 128)
                gen_piece(smem, (c + 1) & 1, P, ks, lane, wid);  // overlap fma with tensor
        }
    }

    // ---- epilogue: denominators to smem, normalize, store ----
    __syncthreads();
    float* ssum = (float*)smem;   // A buffers dead now
    if (wc == 0 && (lane & 3) == 0) {
        #pragma unroll
        for (int s = 0; s < 2; s++) {
            int r = wr * 32 + s * 16 + (lane >> 2);
            ssum[r] = dacc[s][0];
            ssum[r + 8] = dacc[s][2];
        }
    }
    __syncthreads();
    #pragma unroll
    for (int s = 0; s < 2; s++) {
        int rA = wr * 32 + s * 16 + (lane >> 2);
        float inv0 = 1.0f / ssum[rA];
        float inv1 = 1.0f / ssum[rA + 8];
        #pragma unroll
        for (int t = 0; t < 2; t++) {
            int col = wc * 16 + t * 8 + (lane & 3) * 2;
            *(float2*)&out[(size_t)(i0 + rA) * FD + col] =
                make_float2(acc[s][t][0] * inv0, acc[s][t][1] * inv0);
            *(float2*)&out[(size_t)(i0 + rA + 8) * FD + col] =
                make_float2(acc[s][t][2] * inv1, acc[s][t][3] * inv1);
        }
    }
}

// ---------------- launch ----------------
extern "C" void kernel_launch(void* const* d_in, const int* in_sizes, int n_in,
                              void* d_out, int out_size) {
    const float* h   = (const float*)d_in[0];
    const int*   adj = (const int*)d_in[1];
    const float* W   = (const float*)d_in[2];
    const float* a   = (const float*)d_in[3];
    float* out = (float*)d_out;
    (void)in_sizes; (void)n_in; (void)out_size;

    cudaFuncSetAttribute(wh_kernel, cudaFuncAttributeMaxDynamicSharedMemorySize, 99328);
    cudaFuncSetAttribute(gat_main_kernel, cudaFuncAttributeMaxDynamicSharedMemorySize, SMEM_MAIN);

    wh_kernel<<<NN / 64, 512, 99328>>>(h, W, a);
    gat_main_kernel<<<128, 512, SMEM_MAIN>>>(adj, out);
}